// round 7
// baseline (speedup 1.0000x reference)
#include <cuda_runtime.h>
#include <cstdint>
#include <cfloat>

// Sparsemax (d = 4096), persistent CTAs + cross-row software pipelining.
//
// Per row:
//   thr_w = warp_max - 1  (<= M-1 <= tau*; per-warp candidate superset, no
//                          block max barrier needed)
//   compact survivors -> smem, partial (sum,count) -> smem   [barrier 1]
//   warp 0: Michelot iterations on the ~100-element compacted set; resets s_n
//   [barrier 2] ; epilogue out = max(x - tau, 0)
//
// Each persistent CTA issues the NEXT row's global loads before processing
// the current row, hiding DRAM latency under the reduction/Michelot tail.

#define ROW_D     4096
#define THREADS   256
#define NW        (THREADS / 32)
#define V4_PER_T  4
#define GRID_CTAS 608   // 152 SMs x 4 resident CTAs

__global__ __launch_bounds__(THREADS, 4)
void sparsemax_kernel(const float* __restrict__ x, float* __restrict__ out,
                      int n_rows)
{
    __shared__ float2 s_sc[NW];
    __shared__ int    s_n;
    __shared__ float  s_tau;
    __shared__ float  s_buf[ROW_D];   // worst case: all elements survive

    const int tid = threadIdx.x;
    const int wid = tid >> 5;
    const int lid = tid & 31;

    int row = blockIdx.x;
    if (row >= n_rows) return;

    if (tid == 0) s_n = 0;
    __syncthreads();

    // ---- load first row ----
    float4 v[V4_PER_T];
    {
        const float4* __restrict__ xr =
            reinterpret_cast<const float4*>(x + (size_t)row * ROW_D);
#pragma unroll
        for (int i = 0; i < V4_PER_T; ++i)
            v[i] = xr[tid + i * THREADS];
    }

    while (true) {
        // ---- prefetch next row (latency hidden under this row's work) ----
        const int  next     = row + GRID_CTAS;
        const bool has_next = next < n_rows;
        float4 vn[V4_PER_T];
        if (has_next) {
            const float4* __restrict__ xn =
                reinterpret_cast<const float4*>(x + (size_t)next * ROW_D);
#pragma unroll
            for (int i = 0; i < V4_PER_T; ++i)
                vn[i] = xn[tid + i * THREADS];
        }

        // ---- per-warp max -> per-warp seed threshold ----
        float m = -FLT_MAX;
#pragma unroll
        for (int i = 0; i < V4_PER_T; ++i) {
            const float4 q = v[i];
            m = fmaxf(m, fmaxf(fmaxf(q.x, q.y), fmaxf(q.z, q.w)));
        }
#pragma unroll
        for (int o = 16; o > 0; o >>= 1)
            m = fmaxf(m, __shfl_xor_sync(0xFFFFFFFFu, m, o));
        const float thr = m - 1.0f;   // <= M-1 <= tau*  => superset of support

        // ---- compact survivors + partial (sum, count) ----
        float s = 0.0f, c = 0.0f;
        int   myc = 0;
#pragma unroll
        for (int i = 0; i < V4_PER_T; ++i) {
            const float4 q = v[i];
            if (q.x > thr) { s += q.x; c += 1.0f; ++myc; }
            if (q.y > thr) { s += q.y; c += 1.0f; ++myc; }
            if (q.z > thr) { s += q.z; c += 1.0f; ++myc; }
            if (q.w > thr) { s += q.w; c += 1.0f; ++myc; }
        }
        if (myc > 0) {
            int pos = atomicAdd(&s_n, myc);
#pragma unroll
            for (int i = 0; i < V4_PER_T; ++i) {
                const float4 q = v[i];
                if (q.x > thr) s_buf[pos++] = q.x;
                if (q.y > thr) s_buf[pos++] = q.y;
                if (q.z > thr) s_buf[pos++] = q.z;
                if (q.w > thr) s_buf[pos++] = q.w;
            }
        }
#pragma unroll
        for (int o = 16; o > 0; o >>= 1) {
            s += __shfl_xor_sync(0xFFFFFFFFu, s, o);
            c += __shfl_xor_sync(0xFFFFFFFFu, c, o);
        }
        if (lid == 0) s_sc[wid] = make_float2(s, c);
        __syncthreads();                               // barrier 1

        // ---- warp 0: Michelot on the compacted set ----
        if (wid == 0) {
            float S = 0.0f, C = 0.0f;
#pragma unroll
            for (int w = 0; w < NW; ++w) { S += s_sc[w].x; C += s_sc[w].y; }
            const int n = s_n;
            if (lid == 0) s_n = 0;                     // reset for next row

            float tau  = (S - 1.0f) / C;               // iter 1: full candidate set
            int   prev = (int)C;

            for (int iter = 0; iter < 32; ++iter) {
                float ls = 0.0f, lc = 0.0f;
                for (int j = lid; j < n; j += 32) {
                    const float vv = s_buf[j];
                    if (vv > tau) { ls += vv; lc += 1.0f; }
                }
#pragma unroll
                for (int o = 16; o > 0; o >>= 1) {
                    ls += __shfl_xor_sync(0xFFFFFFFFu, ls, o);
                    lc += __shfl_xor_sync(0xFFFFFFFFu, lc, o);
                }
                const int cnt = (int)lc;   // >= 1: row max always above tau
                tau = (ls - 1.0f) / lc;
                if (cnt == prev) break;    // active set unchanged -> exact tau*
                prev = cnt;
            }
            if (lid == 0) s_tau = tau;
        }
        __syncthreads();                               // barrier 2
        const float tau = s_tau;

        // ---- epilogue: out = max(x - tau, 0) ----
        {
            float4* __restrict__ orr =
                reinterpret_cast<float4*>(out + (size_t)row * ROW_D);
#pragma unroll
            for (int i = 0; i < V4_PER_T; ++i) {
                const float4 q = v[i];
                float4 o;
                o.x = fmaxf(q.x - tau, 0.0f);
                o.y = fmaxf(q.y - tau, 0.0f);
                o.z = fmaxf(q.z - tau, 0.0f);
                o.w = fmaxf(q.w - tau, 0.0f);
                orr[tid + i * THREADS] = o;
            }
        }

        if (!has_next) break;
        row = next;
#pragma unroll
        for (int i = 0; i < V4_PER_T; ++i) v[i] = vn[i];
    }
}

extern "C" void kernel_launch(void* const* d_in, const int* in_sizes, int n_in,
                              void* d_out, int out_size)
{
    const float* x   = (const float*)d_in[0];
    float*       out = (float*)d_out;
    const int n_rows = in_sizes[0] / ROW_D;   // 16384
    const int grid   = (n_rows < GRID_CTAS) ? n_rows : GRID_CTAS;
    sparsemax_kernel<<<grid, THREADS>>>(x, out, n_rows);
}